// round 15
// baseline (speedup 1.0000x reference)
#include <cuda_runtime.h>
#include <cuda_fp16.h>
#include <cstdint>
#include <cstddef>

#define B_    8192
#define T_    90
#define F_    7
#define H_    128
#define G_    512      // 4*H
#define D1_   128
#define D2_   64
#define OUT_  30

// -------- device scratch (no cudaMalloc allowed) --------
__device__ __align__(128) float g_hin  [(size_t)B_ * T_ * H_];   // LN(x@W_in^T+b), tf32-rounded
__device__ __align__(128) float g_hout0[(size_t)B_ * T_ * H_];   // layer-0 h outs
__device__ __align__(128) float g_xg   [(size_t)B_ * T_ * G_];   // input projections (+bias), unit-major cols
// Whh packed fp16 k-pair fragments (single term): [L][chunk 4][kk 16][520] u32
__device__ __align__(128) uint32_t g_WP[2 * 4 * 16 * 520];
__device__ float g_biasC[2 * G_];   // bih + bhh, unit-major order

// ======================= common helpers =======================
__device__ __forceinline__ float sgf(float x) {
    return __fdividef(1.0f, 1.0f + __expf(-x));
}
__device__ __forceinline__ float thf(float x) {
    return 2.0f * sgf(2.0f * x) - 1.0f;
}
__device__ __forceinline__ float tf32r(float x) {
    uint32_t t;
    asm("cvt.rna.tf32.f32 %0, %1;" : "=r"(t) : "f"(x));
    return __uint_as_float(t);
}
__device__ __forceinline__ uint16_t f16b(float x) {
    __half h = __float2half_rn(x);
    return *(uint16_t*)&h;
}
__device__ __forceinline__ float f16f(uint16_t u) {
    __half h = *(__half*)&u;
    return __half2float(h);
}
__device__ __forceinline__ void cpa16(uint32_t s, const void* g) {
    asm volatile("cp.async.cg.shared.global [%0], [%1], 16;" :: "r"(s), "l"(g));
}
__device__ __forceinline__ void cpcommit() { asm volatile("cp.async.commit_group;"); }
__device__ __forceinline__ void cpwait0()  { asm volatile("cp.async.wait_group 0;"); }
__device__ __forceinline__ uint32_t smem_u32(const void* p) {
    uint32_t a;
    asm("{ .reg .u64 t; cvta.to.shared.u64 t, %1; cvt.u32.u64 %0, t; }" : "=r"(a) : "l"(p));
    return a;
}
// portable tensor-core mmas (sm_80+ PTX, run as HMMA on sm_103)
__device__ __forceinline__ void mma_tf32(float* d, const uint32_t* a, const uint32_t* b) {
    asm("mma.sync.aligned.m16n8k8.row.col.f32.tf32.tf32.f32 "
        "{%0,%1,%2,%3}, {%4,%5,%6,%7}, {%8,%9}, {%0,%1,%2,%3};"
        : "+f"(d[0]), "+f"(d[1]), "+f"(d[2]), "+f"(d[3])
        : "r"(a[0]), "r"(a[1]), "r"(a[2]), "r"(a[3]), "r"(b[0]), "r"(b[1]));
}
__device__ __forceinline__ void mma_f16(float* d, const uint32_t* a, const uint32_t* b) {
    asm("mma.sync.aligned.m16n8k16.row.col.f32.f16.f16.f32 "
        "{%0,%1,%2,%3}, {%4,%5,%6,%7}, {%8,%9}, {%0,%1,%2,%3};"
        : "+f"(d[0]), "+f"(d[1]), "+f"(d[2]), "+f"(d[3])
        : "r"(a[0]), "r"(a[1]), "r"(a[2]), "r"(a[3]), "r"(b[0]), "r"(b[1]));
}

// ======================= K0: weight repack =======================
// n_phys = unit*4 + gate (gate: 0=i,1=f,2=g,3=o); source row = gate*128 + unit.
// g_WP[L][c4][kk16][520]: u32 = pack(fp16 W[k0], fp16 W[k0+1]), k0 = c*32 + kk*2.
__global__ void prep_kernel(const float* __restrict__ Whh0, const float* __restrict__ bih0,
                            const float* __restrict__ bhh0, const float* __restrict__ Whh1,
                            const float* __restrict__ bih1, const float* __restrict__ bhh1) {
    int idx = blockIdx.x * blockDim.x + threadIdx.x;
    const int per_l = 4 * 16 * 520;   // 33280 per layer
    if (idx < 2 * per_l) {
        int L = idx / per_l;
        int r = idx % per_l;
        int c = r / (16 * 520);
        int kk = (r / 520) % 16;
        int n = r % 520;
        uint32_t p = 0;
        if (n < 512) {
            const float* Whh = L ? Whh1 : Whh0;
            int u = n >> 2, g = n & 3;
            const float* src = Whh + (size_t)(g * 128 + u) * H_ + (c * 32 + kk * 2);
            p = ((uint32_t)f16b(src[1]) << 16) | f16b(src[0]);
        }
        g_WP[((L * 4 + c) * 16 + kk) * 520 + n] = p;
    }
    if (idx < 2 * G_) {
        int L = idx >> 9, n = idx & 511;
        int u = n >> 2, g = n & 3;
        const float* bih = L ? bih1 : bih0;
        const float* bhh = L ? bhh1 : bhh0;
        g_biasC[idx] = bih[g * 128 + u] + bhh[g * 128 + u];
    }
}

// ============ K1: input projection + layernorm (warp per row) ============
__global__ void __launch_bounds__(256) proj_ln_kernel(
    const float* __restrict__ x, const float* __restrict__ W_in,
    const float* __restrict__ b_in, const float* __restrict__ g_in,
    const float* __restrict__ be_in) {
    __shared__ float Ws[H_ * F_];
    __shared__ float bs[H_], gs[H_], es[H_];
    int tid = threadIdx.x;
    for (int i = tid; i < H_ * F_; i += 256) Ws[i] = W_in[i];
    if (tid < H_) { bs[tid] = b_in[tid]; gs[tid] = g_in[tid]; es[tid] = be_in[tid]; }
    __syncthreads();

    int warp = tid >> 5, lane = tid & 31;
    int row = blockIdx.x * 8 + warp;

    float xv = (lane < F_) ? x[(size_t)row * F_ + lane] : 0.0f;
    float y[4];
#pragma unroll
    for (int j = 0; j < 4; j++) {
        int h = lane + 32 * j;
        float a = bs[h];
#pragma unroll
        for (int f = 0; f < F_; f++) {
            float xf = __shfl_sync(0xffffffffu, xv, f);
            a = fmaf(xf, Ws[h * F_ + f], a);
        }
        y[j] = a;
    }
    float s = y[0] + y[1] + y[2] + y[3];
#pragma unroll
    for (int o = 16; o; o >>= 1) s += __shfl_xor_sync(0xffffffffu, s, o);
    float mu = s * (1.0f / H_);
    float v = 0.0f;
#pragma unroll
    for (int j = 0; j < 4; j++) { float d = y[j] - mu; v += d * d; }
#pragma unroll
    for (int o = 16; o; o >>= 1) v += __shfl_xor_sync(0xffffffffu, v, o);
    float rstd = rsqrtf(v * (1.0f / H_) + 1e-5f);
#pragma unroll
    for (int j = 0; j < 4; j++) {
        int h = lane + 32 * j;
        g_hin[(size_t)row * H_ + h] = tf32r((y[j] - mu) * rstd * gs[h] + es[h]);
    }
}

// ============ K2: xg = in @ Wih^T + bias   (mma.sync tf32, unit-major cols) ============
#define GXG_OFF_B   67584
#define GXG_OFF_BI  202752
#define GXG_SMEM    203776
#define N_MTILES    ((B_ * T_) / 128)   // 5760

__global__ void __launch_bounds__(256, 1) gemm_xg_kernel(
    const float* __restrict__ Wih0, const float* __restrict__ Wih1, int layer) {
    extern __shared__ char smem[];
    float* As    = (float*)smem;
    float* Bs    = (float*)(smem + GXG_OFF_B);
    float* biasS = (float*)(smem + GXG_OFF_BI);
    const uint32_t asAddr = smem_u32(As);

    const int tid  = threadIdx.x;
    const int lane = tid & 31, wid = tid >> 5;
    const int wm = wid & 1, wn = wid >> 1;
    const int lrow = lane >> 2, lcol = lane & 3;
    const int nh = blockIdx.x & 1, slot = blockIdx.x >> 1;

    const float* in = layer ? g_hout0 : g_hin;
    const float* W  = layer ? Wih1 : Wih0;   // full, indexed via n_phys mapping

    for (int idx = tid; idx < 256 * H_; idx += 256) {
        int n = idx >> 7, k = idx & 127;
        int np = nh * 256 + n;               // physical (unit-major) column
        Bs[n * 132 + k] = tf32r(W[(size_t)((np & 3) * 128 + (np >> 2)) * H_ + k]);
    }
    for (int i = tid; i < 256; i += 256) biasS[i] = g_biasC[layer * G_ + nh * 256 + i];
    __syncthreads();

    float bC[8][2];
#pragma unroll
    for (int nf = 0; nf < 8; nf++) {
        int c = wn * 64 + nf * 8 + 2 * lcol;
        bC[nf][0] = biasS[c];
        bC[nf][1] = biasS[c + 1];
    }

    auto copyA = [&](int m0) {
#pragma unroll 4
        for (int u = tid; u < 4096; u += 256) {
            int r = u >> 5, q = u & 31;
            cpa16(asAddr + (uint32_t)(r * 132 + q * 4) * 4,
                  in + (size_t)(m0 + r) * H_ + q * 4);
        }
        cpcommit();
    };

    int mt = slot;
    if (mt < N_MTILES) copyA(mt * 128);
    for (; mt < N_MTILES; mt += 74) {
        const int m0 = mt * 128;
        cpwait0();
        __syncthreads();

        float acc[4][8][4];
#pragma unroll
        for (int mf = 0; mf < 4; mf++)
#pragma unroll
            for (int nf = 0; nf < 8; nf++)
#pragma unroll
                for (int q = 0; q < 4; q++) acc[mf][nf][q] = 0.0f;

        const float* Aw = As + (wm * 64 + lrow) * 132 + lcol;
        const float* Bw = Bs + (wn * 64 + lrow) * 132 + lcol;
#pragma unroll
        for (int ks = 0; ks < 16; ks++) {
            const int k0 = ks * 8;
            uint32_t a[4][4], b[8][2];
#pragma unroll
            for (int mf = 0; mf < 4; mf++) {
                const float* p = Aw + mf * 16 * 132 + k0;
                a[mf][0] = __float_as_uint(p[0]);
                a[mf][1] = __float_as_uint(p[8 * 132]);
                a[mf][2] = __float_as_uint(p[4]);
                a[mf][3] = __float_as_uint(p[8 * 132 + 4]);
            }
#pragma unroll
            for (int nf = 0; nf < 8; nf++) {
                const float* p = Bw + nf * 8 * 132 + k0;
                b[nf][0] = __float_as_uint(p[0]);
                b[nf][1] = __float_as_uint(p[4]);
            }
#pragma unroll
            for (int mf = 0; mf < 4; mf++)
#pragma unroll
                for (int nf = 0; nf < 8; nf++)
                    mma_tf32(acc[mf][nf], a[mf], b[nf]);
        }
        __syncthreads();
        if (mt + 74 < N_MTILES) copyA((mt + 74) * 128);

#pragma unroll
        for (int mf = 0; mf < 4; mf++) {
            int r0 = m0 + wm * 64 + mf * 16 + lrow;
            float* o0 = g_xg + (size_t)r0 * G_ + nh * 256 + wn * 64;
            float* o1 = o0 + (size_t)8 * G_;
#pragma unroll
            for (int nf = 0; nf < 8; nf++) {
                int c = nf * 8 + 2 * lcol;
                float2 v0 = make_float2(acc[mf][nf][0] + bC[nf][0],
                                        acc[mf][nf][1] + bC[nf][1]);
                float2 v1 = make_float2(acc[mf][nf][2] + bC[nf][0],
                                        acc[mf][nf][3] + bC[nf][1]);
                *(float2*)(o0 + c) = v0;
                *(float2*)(o1 + c) = v1;
            }
        }
    }
}

// ============ K3: sequential recurrence (fp16 2-term mma, RESIDENT weights) ============
// 128 CTAs x 256 threads (8 warps, 1m x 8n), 64 batch rows per CTA.
// Whole layer weight set (133120 B) loaded into smem ONCE; 2 syncs per step.
// smem map (201728 B/CTA):
//   [0,17408)        AP hi  u32[64][68]   (h packed fp16 pairs, k = unit)
//   [17408,34816)    AP lo
//   [34816,68608)    hstage f32[64][132]
//   [68608,201728)   W resident: [c4][kk16][520] u32 (133120 B)
#define APHI_OFF   0
#define APLO_OFF   17408
#define HST_OFF    34816
#define HSTRIDE    132
#define WSM_OFF    68608
#define WCHUNK_U32 (16 * 520)   // 8320 u32 per chunk
#define WTOT_U32   (4 * WCHUNK_U32)
#define SQ_SMEM    201728

__global__ void __launch_bounds__(256, 1) lstm_seq_kernel(
    int layer,
    const float* __restrict__ g_ln, const float* __restrict__ be_ln,
    const float* __restrict__ W_d1, const float* __restrict__ b_d1,
    const float* __restrict__ W_d2, const float* __restrict__ b_d2,
    const float* __restrict__ W_d3, const float* __restrict__ b_d3,
    float* __restrict__ out) {
    extern __shared__ char smem[];
    float* hstage = (float*)(smem + HST_OFF);
    const uint32_t* aphi = (const uint32_t*)(smem + APHI_OFF);
    const uint32_t* aplo = (const uint32_t*)(smem + APLO_OFF);
    const uint32_t* wsm  = (const uint32_t*)(smem + WSM_OFF);

    const int tid = threadIdx.x;
    const int lane = tid & 31, wn = tid >> 5;
    const int qid = lane >> 2, j = lane & 3;
    const int row0 = blockIdx.x * 64;
    const uint32_t sb = smem_u32(smem);
    const uint32_t* wpL = g_WP + (size_t)layer * WTOT_U32;

    float acc[4][8][4];
    float cst[4][8];
#pragma unroll
    for (int mf = 0; mf < 4; mf++)
#pragma unroll
        for (int nt = 0; nt < 8; nt++) cst[mf][nt] = 0.0f;

    // ---- one-time: whole weight set -> smem; zero AP (h = 0) ----
    for (int u = tid; u < WTOT_U32 / 4; u += 256)
        cpa16(sb + WSM_OFF + u * 16, (const float4*)wpL + u);
    cpcommit();
    for (int i = tid; i < 2 * 64 * 68; i += 256)
        ((uint32_t*)smem)[i] = 0;   // APhi+APlo contiguous
    cpwait0();
    __syncthreads();

    for (int t = 0; t < T_; ++t) {
        // ---- acc <- xg (unit-major, bias folded) ----
#pragma unroll
        for (int mf = 0; mf < 4; mf++) {
            const float* x1 = g_xg + ((size_t)(row0 + mf * 16 + qid) * T_ + t) * G_;
            const float* x2 = x1 + (size_t)8 * T_ * G_;
#pragma unroll
            for (int nt = 0; nt < 8; nt++) {
                int c = wn * 64 + nt * 8 + 2 * j;
                float2 v1 = *(const float2*)(x1 + c);
                float2 v2 = *(const float2*)(x2 + c);
                acc[mf][nt][0] = v1.x; acc[mf][nt][1] = v1.y;
                acc[mf][nt][2] = v2.x; acc[mf][nt][3] = v2.y;
            }
        }
        // ---- layer-0: stream previous step's h to global (coalesced) ----
        if (layer == 0 && t > 0) {
#pragma unroll
            for (int k = 0; k < 8; k++) {
                int idx = tid + k * 256;
                int r = idx >> 5, c4 = (idx & 31) * 4;
                float4 v = *(const float4*)(hstage + r * HSTRIDE + c4);
                *(float4*)(g_hout0 + ((size_t)(row0 + r) * T_ + (t - 1)) * H_ + c4) = v;
            }
        }
        // ---- h @ Whh^T via fp16 2-term mma, resident weights, no waits ----
        if (t) {
#pragma unroll
            for (int c = 0; c < 4; ++c) {
                const uint32_t* wb = wsm + c * WCHUNK_U32;
#pragma unroll
                for (int lkt = 0; lkt < 2; ++lkt) {
                    const int kb = c * 16 + lkt * 8 + j;
                    uint32_t ah[4][4], al[4][4];
#pragma unroll
                    for (int mf = 0; mf < 4; ++mf) {
                        const uint32_t* p1 = aphi + (mf * 16 + qid) * 68;
                        const uint32_t* p2 = p1 + 8 * 68;
                        ah[mf][0] = p1[kb];     ah[mf][1] = p2[kb];
                        ah[mf][2] = p1[kb + 4]; ah[mf][3] = p2[kb + 4];
                        const uint32_t* q1 = aplo + (mf * 16 + qid) * 68;
                        const uint32_t* q2 = q1 + 8 * 68;
                        al[mf][0] = q1[kb];     al[mf][1] = q2[kb];
                        al[mf][2] = q1[kb + 4]; al[mf][3] = q2[kb + 4];
                    }
                    const uint32_t* w0 = wb + (lkt * 8 + j) * 520;
                    const uint32_t* w1 = w0 + 4 * 520;
#pragma unroll
                    for (int nt = 0; nt < 8; ++nt) {
                        int n = wn * 64 + nt * 8 + qid;
                        uint32_t bw[2] = { w0[n], w1[n] };
                        mma_f16(acc[0][nt], ah[0], bw);
                        mma_f16(acc[1][nt], ah[1], bw);
                        mma_f16(acc[2][nt], ah[2], bw);
                        mma_f16(acc[3][nt], ah[3], bw);
                        mma_f16(acc[0][nt], al[0], bw);
                        mma_f16(acc[1][nt], al[1], bw);
                        mma_f16(acc[2][nt], al[2], bw);
                        mma_f16(acc[3][nt], al[3], bw);
                    }
                }
            }
        }
        __syncthreads();   // all mma reads of AP done; hstage STG reads done

        // ---- activations: shfl-pair (i,f)<->(g,o), update c, emit h ----
        const bool ev = (lane & 1) == 0;
        const bool keep_h = (layer == 0) || (t == T_ - 1);
#pragma unroll
        for (int mf = 0; mf < 4; ++mf) {
            int r1 = mf * 16 + qid;
#pragma unroll
            for (int nt = 0; nt < 8; ++nt) {
                float x0 = __shfl_xor_sync(0xffffffffu, acc[mf][nt][0], 1);
                float x1 = __shfl_xor_sync(0xffffffffu, acc[mf][nt][1], 1);
                float x2 = __shfl_xor_sync(0xffffffffu, acc[mf][nt][2], 1);
                float x3 = __shfl_xor_sync(0xffffffffu, acc[mf][nt][3], 1);
                float iv = ev ? acc[mf][nt][0] : x2;
                float fv = ev ? acc[mf][nt][1] : x3;
                float gv = ev ? x0 : acc[mf][nt][2];
                float ov = ev ? x1 : acc[mf][nt][3];
                float c = cst[mf][nt];
                c = sgf(fv) * c + sgf(iv) * thf(gv);
                cst[mf][nt] = c;
                float h = sgf(ov) * thf(c);
                int row = ev ? r1 : (r1 + 8);
                int u = wn * 16 + nt * 2 + ((lane >> 1) & 1);
                uint16_t hh = f16b(h);
                uint16_t hl = f16b(h - f16f(hh));
                uint32_t off = (uint32_t)(row * 68 + (u >> 1)) * 4 + (u & 1) * 2;
                *(uint16_t*)(smem + APHI_OFF + off) = hh;
                *(uint16_t*)(smem + APLO_OFF + off) = hl;
                if (keep_h) hstage[row * HSTRIDE + u] = h;
            }
        }
        __syncthreads();   // AP/hstage ready for next step
    } // t

    if (layer == 0) {
        // final h(T-1) -> g_hout0
#pragma unroll
        for (int k = 0; k < 8; k++) {
            int idx = tid + k * 256;
            int r = idx >> 5, c4 = (idx & 31) * 4;
            float4 v = *(const float4*)(hstage + r * HSTRIDE + c4);
            *(float4*)(g_hout0 + ((size_t)(row0 + r) * T_ + (T_ - 1)) * H_ + c4) = v;
        }
        return;
    }

    // =================== dense head (final h in hstage, 64 rows) ===================
    float* lnS = (float*)(smem + WSM_OFF);            // [64][128] = 32KB (weights dead now)
    float* d1S = (float*)(smem + WSM_OFF + 32768);    // [64][128] = 32KB
    float* d2S = lnS;                                 // reuse after d1 built

    if (tid < 64) {
        int r = tid;
        const float* hr = hstage + r * HSTRIDE;
        float s = 0.0f;
        for (int k = 0; k < H_; k++) s += hr[k];
        float mu = s * (1.0f / H_);
        float v = 0.0f;
        for (int k = 0; k < H_; k++) { float d = hr[k] - mu; v += d * d; }
        float rstd = rsqrtf(v * (1.0f / H_) + 1e-5f);
        for (int k = 0; k < H_; k++)
            lnS[r * H_ + k] = (hr[k] - mu) * rstd * __ldg(g_ln + k) + __ldg(be_ln + k);
    }
    __syncthreads();

    // d1 = relu(ln @ W_d1^T + b_d1): weights direct from global (L1/L2-cached)
    {
        int r = tid >> 2, c0 = (tid & 3) * 32;
        for (int c = c0; c < c0 + 32; c++) {
            float a = __ldg(b_d1 + c);
            const float4* lp = (const float4*)(lnS + r * H_);
            const float4* wp = (const float4*)(W_d1 + (size_t)c * H_);
#pragma unroll 8
            for (int k4 = 0; k4 < H_ / 4; k4++) {
                float4 l = lp[k4], w = __ldg(wp + k4);
                a = fmaf(l.x, w.x, fmaf(l.y, w.y, fmaf(l.z, w.z, fmaf(l.w, w.w, a))));
            }
            d1S[r * D1_ + c] = fmaxf(a, 0.0f);
        }
    }
    __syncthreads();

    // d2 = relu(d1 @ W_d2^T + b_d2)
    {
        int r = tid >> 2, c0 = (tid & 3) * 16;
        for (int c = c0; c < c0 + 16; c++) {
            float a = __ldg(b_d2 + c);
            const float4* dp = (const float4*)(d1S + r * D1_);
            const float4* wp = (const float4*)(W_d2 + (size_t)c * D1_);
#pragma unroll 8
            for (int k4 = 0; k4 < D1_ / 4; k4++) {
                float4 l = dp[k4], w = __ldg(wp + k4);
                a = fmaf(l.x, w.x, fmaf(l.y, w.y, fmaf(l.z, w.z, fmaf(l.w, w.w, a))));
            }
            d2S[r * D2_ + c] = fmaxf(a, 0.0f);
        }
    }
    __syncthreads();

    // out = d2 @ W_d3^T + b_d3
    for (int idx = tid; idx < 64 * OUT_; idx += 256) {
        int r = idx / OUT_, c = idx % OUT_;
        float a = __ldg(b_d3 + c);
        const float* dp = d2S + r * D2_;
        const float* wp = W_d3 + (size_t)c * D2_;
#pragma unroll 8
        for (int k = 0; k < D2_; k++) a = fmaf(dp[k], __ldg(wp + k), a);
        out[(size_t)(row0 + r) * OUT_ + c] = a;
    }
}

// ======================= launch =======================
extern "C" void kernel_launch(void* const* d_in, const int* in_sizes, int n_in,
                              void* d_out, int out_size) {
    (void)in_sizes; (void)n_in; (void)out_size;
    const float* x     = (const float*)d_in[0];
    const float* W_in  = (const float*)d_in[1];
    const float* b_in  = (const float*)d_in[2];
    const float* g_in  = (const float*)d_in[3];
    const float* be_in = (const float*)d_in[4];
    const float* Wih0  = (const float*)d_in[5];
    const float* Whh0  = (const float*)d_in[6];
    const float* bih0  = (const float*)d_in[7];
    const float* bhh0  = (const float*)d_in[8];
    const float* Wih1  = (const float*)d_in[9];
    const float* Whh1  = (const float*)d_in[10];
    const float* bih1  = (const float*)d_in[11];
    const float* bhh1  = (const float*)d_in[12];
    const float* g_ln  = (const float*)d_in[13];
    const float* be_ln = (const float*)d_in[14];
    const float* W_d1  = (const float*)d_in[15];
    const float* b_d1  = (const float*)d_in[16];
    const float* W_d2  = (const float*)d_in[17];
    const float* b_d2  = (const float*)d_in[18];
    const float* W_d3  = (const float*)d_in[19];
    const float* b_d3  = (const float*)d_in[20];
    float* out = (float*)d_out;

    cudaFuncSetAttribute(gemm_xg_kernel, cudaFuncAttributeMaxDynamicSharedMemorySize, GXG_SMEM);
    cudaFuncSetAttribute(lstm_seq_kernel, cudaFuncAttributeMaxDynamicSharedMemorySize, SQ_SMEM);

    prep_kernel<<<260, 256>>>(Whh0, bih0, bhh0, Whh1, bih1, bhh1);
    proj_ln_kernel<<<(B_ * T_) / 8, 256>>>(x, W_in, b_in, g_in, be_in);

    gemm_xg_kernel<<<148, 256, GXG_SMEM>>>(Wih0, Wih1, 0);
    lstm_seq_kernel<<<B_ / 64, 256, SQ_SMEM>>>(0, g_ln, be_ln, W_d1, b_d1,
                                               W_d2, b_d2, W_d3, b_d3, out);
    gemm_xg_kernel<<<148, 256, GXG_SMEM>>>(Wih0, Wih1, 1);
    lstm_seq_kernel<<<B_ / 64, 256, SQ_SMEM>>>(1, g_ln, be_ln, W_d1, b_d1,
                                               W_d2, b_d2, W_d3, b_d3, out);
}

// round 16
// speedup vs baseline: 1.1923x; 1.1923x over previous
#include <cuda_runtime.h>
#include <cuda_fp16.h>
#include <cstdint>
#include <cstddef>

#define B_    8192
#define T_    90
#define F_    7
#define H_    128
#define G_    512      // 4*H
#define D1_   128
#define D2_   64
#define OUT_  30

// -------- device scratch (no cudaMalloc allowed) --------
__device__ __align__(128) __half g_hin  [(size_t)B_ * T_ * H_];  // LN(x@W_in^T+b), fp16
__device__ __align__(128) __half g_hout0[(size_t)B_ * T_ * H_];  // layer-0 h outs, fp16
__device__ __align__(128) __half g_xg   [(size_t)B_ * T_ * G_];  // input projections (+bias), fp16, unit-major
// Whh packed fp16 k-pair fragments (single term): [L][chunk 4][kk 16][520] u32
__device__ __align__(128) uint32_t g_WP[2 * 4 * 16 * 520];
__device__ float g_biasC[2 * G_];   // bih + bhh, unit-major order

// ======================= common helpers =======================
__device__ __forceinline__ float sgf(float x) {
    return __fdividef(1.0f, 1.0f + __expf(-x));
}
__device__ __forceinline__ float thf(float x) {
    return 2.0f * sgf(2.0f * x) - 1.0f;
}
__device__ __forceinline__ uint16_t f16b(float x) {
    __half h = __float2half_rn(x);
    return *(uint16_t*)&h;
}
__device__ __forceinline__ float f16f(uint16_t u) {
    __half h = *(__half*)&u;
    return __half2float(h);
}
__device__ __forceinline__ void cpa16(uint32_t s, const void* g) {
    asm volatile("cp.async.cg.shared.global [%0], [%1], 16;" :: "r"(s), "l"(g));
}
__device__ __forceinline__ void cpcommit() { asm volatile("cp.async.commit_group;"); }
__device__ __forceinline__ void cpwait0()  { asm volatile("cp.async.wait_group 0;"); }
__device__ __forceinline__ uint32_t smem_u32(const void* p) {
    uint32_t a;
    asm("{ .reg .u64 t; cvta.to.shared.u64 t, %1; cvt.u32.u64 %0, t; }" : "=r"(a) : "l"(p));
    return a;
}
// portable tensor-core mma (sm_80+ PTX, runs as HMMA on sm_103)
__device__ __forceinline__ void mma_f16(float* d, const uint32_t* a, const uint32_t* b) {
    asm("mma.sync.aligned.m16n8k16.row.col.f32.f16.f16.f32 "
        "{%0,%1,%2,%3}, {%4,%5,%6,%7}, {%8,%9}, {%0,%1,%2,%3};"
        : "+f"(d[0]), "+f"(d[1]), "+f"(d[2]), "+f"(d[3])
        : "r"(a[0]), "r"(a[1]), "r"(a[2]), "r"(a[3]), "r"(b[0]), "r"(b[1]));
}

// ======================= K0: weight repack =======================
// n_phys = unit*4 + gate (gate: 0=i,1=f,2=g,3=o); source row = gate*128 + unit.
// g_WP[L][c4][kk16][520]: u32 = pack(fp16 W[k0], fp16 W[k0+1]), k0 = c*32 + kk*2.
__global__ void prep_kernel(const float* __restrict__ Whh0, const float* __restrict__ bih0,
                            const float* __restrict__ bhh0, const float* __restrict__ Whh1,
                            const float* __restrict__ bih1, const float* __restrict__ bhh1) {
    int idx = blockIdx.x * blockDim.x + threadIdx.x;
    const int per_l = 4 * 16 * 520;   // 33280 per layer
    if (idx < 2 * per_l) {
        int L = idx / per_l;
        int r = idx % per_l;
        int c = r / (16 * 520);
        int kk = (r / 520) % 16;
        int n = r % 520;
        uint32_t p = 0;
        if (n < 512) {
            const float* Whh = L ? Whh1 : Whh0;
            int u = n >> 2, g = n & 3;
            const float* src = Whh + (size_t)(g * 128 + u) * H_ + (c * 32 + kk * 2);
            p = ((uint32_t)f16b(src[1]) << 16) | f16b(src[0]);
        }
        g_WP[((L * 4 + c) * 16 + kk) * 520 + n] = p;
    }
    if (idx < 2 * G_) {
        int L = idx >> 9, n = idx & 511;
        int u = n >> 2, g = n & 3;
        const float* bih = L ? bih1 : bih0;
        const float* bhh = L ? bhh1 : bhh0;
        g_biasC[idx] = bih[g * 128 + u] + bhh[g * 128 + u];
    }
}

// ============ K1: input projection + layernorm (warp per row, fp16 out) ============
__global__ void __launch_bounds__(256) proj_ln_kernel(
    const float* __restrict__ x, const float* __restrict__ W_in,
    const float* __restrict__ b_in, const float* __restrict__ g_in,
    const float* __restrict__ be_in) {
    __shared__ float Ws[H_ * F_];
    __shared__ float bs[H_], gs[H_], es[H_];
    int tid = threadIdx.x;
    for (int i = tid; i < H_ * F_; i += 256) Ws[i] = W_in[i];
    if (tid < H_) { bs[tid] = b_in[tid]; gs[tid] = g_in[tid]; es[tid] = be_in[tid]; }
    __syncthreads();

    int warp = tid >> 5, lane = tid & 31;
    int row = blockIdx.x * 8 + warp;

    float xv = (lane < F_) ? x[(size_t)row * F_ + lane] : 0.0f;
    float y[4];
#pragma unroll
    for (int j = 0; j < 4; j++) {
        int h = lane * 4 + j;             // contiguous 4 per lane -> vector store
        float a = bs[h];
#pragma unroll
        for (int f = 0; f < F_; f++) {
            float xf = __shfl_sync(0xffffffffu, xv, f);
            a = fmaf(xf, Ws[h * F_ + f], a);
        }
        y[j] = a;
    }
    float s = y[0] + y[1] + y[2] + y[3];
#pragma unroll
    for (int o = 16; o; o >>= 1) s += __shfl_xor_sync(0xffffffffu, s, o);
    float mu = s * (1.0f / H_);
    float v = 0.0f;
#pragma unroll
    for (int j = 0; j < 4; j++) { float d = y[j] - mu; v += d * d; }
#pragma unroll
    for (int o = 16; o; o >>= 1) v += __shfl_xor_sync(0xffffffffu, v, o);
    float rstd = rsqrtf(v * (1.0f / H_) + 1e-5f);

    float o[4];
#pragma unroll
    for (int j = 0; j < 4; j++) {
        int h = lane * 4 + j;
        o[j] = (y[j] - mu) * rstd * gs[h] + es[h];
    }
    __half2 p0 = __floats2half2_rn(o[0], o[1]);
    __half2 p1 = __floats2half2_rn(o[2], o[3]);
    uint2 u;
    u.x = *(uint32_t*)&p0;
    u.y = *(uint32_t*)&p1;
    *(uint2*)(g_hin + (size_t)row * H_ + lane * 4) = u;
}

// ============ K2: xg = in @ Wih^T + bias   (mma.sync fp16, unit-major cols) ============
// CTA 256 thr, tile 128M x 256N, K=128. warps 2m x 4n, warp tile 64x64.
// smem: As u32[128][68] 34816 | Bs u32[256][68] 69632 | bias 1KB = 105472 B
#define GX2_OFF_B   34816
#define GX2_OFF_BI  104448
#define GX2_SMEM    105472
#define N_MTILES    ((B_ * T_) / 128)   // 5760

__global__ void __launch_bounds__(256, 1) gemm_xg_kernel(
    const float* __restrict__ Wih0, const float* __restrict__ Wih1, int layer) {
    extern __shared__ char smem[];
    uint32_t* As = (uint32_t*)smem;                   // [128][68] fp16 pairs
    uint32_t* Bs = (uint32_t*)(smem + GX2_OFF_B);     // [256][68] fp16 pairs
    float* biasS = (float*)(smem + GX2_OFF_BI);
    const uint32_t asAddr = smem_u32(As);

    const int tid  = threadIdx.x;
    const int lane = tid & 31, wid = tid >> 5;
    const int wm = wid & 1, wn = wid >> 1;
    const int lrow = lane >> 2, lcol = lane & 3;
    const int nh = blockIdx.x & 1, slot = blockIdx.x >> 1;

    const __half* in = layer ? g_hout0 : g_hin;
    const float* W   = layer ? Wih1 : Wih0;   // indexed via n_phys mapping

    // ---- one-time: weights -> smem fp16, bias ----
    for (int idx = tid; idx < 256 * H_; idx += 256) {
        int n = idx >> 7, k = idx & 127;
        int np = nh * 256 + n;               // physical (unit-major) column
        float w = W[(size_t)((np & 3) * 128 + (np >> 2)) * H_ + k];
        *(uint16_t*)(smem + GX2_OFF_B + (n * 68 + (k >> 1)) * 4 + (k & 1) * 2) = f16b(w);
    }
    for (int i = tid; i < 256; i += 256) biasS[i] = g_biasC[layer * G_ + nh * 256 + i];
    __syncthreads();

    float bC[8][2];
#pragma unroll
    for (int nf = 0; nf < 8; nf++) {
        int c = wn * 64 + nf * 8 + 2 * lcol;
        bC[nf][0] = biasS[c];
        bC[nf][1] = biasS[c + 1];
    }

    auto copyA = [&](int m0) {
#pragma unroll 4
        for (int u = tid; u < 2048; u += 256) {
            int r = u >> 4, q = u & 15;     // 16B = 8 halves per chunk
            cpa16(asAddr + (uint32_t)(r * 68 + q * 4) * 4,
                  in + (size_t)(m0 + r) * H_ + q * 8);
        }
        cpcommit();
    };

    int mt = slot;
    if (mt < N_MTILES) copyA(mt * 128);
    for (; mt < N_MTILES; mt += 74) {
        const int m0 = mt * 128;
        cpwait0();
        __syncthreads();

        float acc[4][8][4];
#pragma unroll
        for (int mf = 0; mf < 4; mf++)
#pragma unroll
            for (int nf = 0; nf < 8; nf++)
#pragma unroll
                for (int q = 0; q < 4; q++) acc[mf][nf][q] = 0.0f;

#pragma unroll
        for (int kbb = 0; kbb < 8; kbb++) {    // k16 blocks
            uint32_t a[4][4], b[8][2];
#pragma unroll
            for (int mf = 0; mf < 4; mf++) {
                const uint32_t* Ar = As + (wm * 64 + mf * 16 + lrow) * 68 + kbb * 8;
                a[mf][0] = Ar[lcol];
                a[mf][1] = Ar[8 * 68 + lcol];
                a[mf][2] = Ar[lcol + 4];
                a[mf][3] = Ar[8 * 68 + lcol + 4];
            }
#pragma unroll
            for (int nf = 0; nf < 8; nf++) {
                const uint32_t* Br = Bs + (wn * 64 + nf * 8 + lrow) * 68 + kbb * 8;
                b[nf][0] = Br[lcol];
                b[nf][1] = Br[lcol + 4];
            }
#pragma unroll
            for (int mf = 0; mf < 4; mf++)
#pragma unroll
                for (int nf = 0; nf < 8; nf++)
                    mma_f16(acc[mf][nf], a[mf], b[nf]);
        }
        __syncthreads();
        if (mt + 74 < N_MTILES) copyA((mt + 74) * 128);

        // ---- epilogue: bias add + fp16 store ----
#pragma unroll
        for (int mf = 0; mf < 4; mf++) {
            int r0 = m0 + wm * 64 + mf * 16 + lrow;
            __half* o0 = g_xg + (size_t)r0 * G_ + nh * 256 + wn * 64;
            __half* o1 = o0 + (size_t)8 * G_;
#pragma unroll
            for (int nf = 0; nf < 8; nf++) {
                int c = nf * 8 + 2 * lcol;
                __half2 v0 = __floats2half2_rn(acc[mf][nf][0] + bC[nf][0],
                                               acc[mf][nf][1] + bC[nf][1]);
                __half2 v1 = __floats2half2_rn(acc[mf][nf][2] + bC[nf][0],
                                               acc[mf][nf][3] + bC[nf][1]);
                *(uint32_t*)(o0 + c) = *(uint32_t*)&v0;
                *(uint32_t*)(o1 + c) = *(uint32_t*)&v1;
            }
        }
    }
}

// ============ K3: sequential recurrence (fp16 2-term mma, streamed weights — R14) ============
// 128 CTAs x 256 threads (8 warps, 1m x 8n), 64 batch rows per CTA.
// smem map (135168 B/CTA):
//   [0,17408)        AP hi  u32[64][68]   (h packed fp16 pairs, k = unit)
//   [17408,34816)    AP lo
//   [34816,68608)    hstage f32[64][132]
//   [68608,101888)   wbuf0: [kk16][520] u32 (33280 B)
//   [101888,135168)  wbuf1
#define APHI_OFF   0
#define APLO_OFF   17408
#define HST_OFF    34816
#define HSTRIDE    132
#define WB0_OFF    68608
#define WB1_OFF    101888
#define WCHUNK_U32 (16 * 520)   // 8320
#define SQ_SMEM    135168

__global__ void __launch_bounds__(256, 1) lstm_seq_kernel(
    int layer,
    const float* __restrict__ g_ln, const float* __restrict__ be_ln,
    const float* __restrict__ W_d1, const float* __restrict__ b_d1,
    const float* __restrict__ W_d2, const float* __restrict__ b_d2,
    const float* __restrict__ W_d3, const float* __restrict__ b_d3,
    float* __restrict__ out) {
    extern __shared__ char smem[];
    float* hstage = (float*)(smem + HST_OFF);
    const uint32_t* aphi = (const uint32_t*)(smem + APHI_OFF);
    const uint32_t* aplo = (const uint32_t*)(smem + APLO_OFF);

    const int tid = threadIdx.x;
    const int lane = tid & 31, wn = tid >> 5;
    const int qid = lane >> 2, j = lane & 3;
    const int row0 = blockIdx.x * 64;
    const uint32_t sb = smem_u32(smem);
    const uint32_t* wpL = g_WP + (size_t)layer * 4 * WCHUNK_U32;

    float acc[4][8][4];
    float cst[4][8];
#pragma unroll
    for (int mf = 0; mf < 4; mf++)
#pragma unroll
        for (int nt = 0; nt < 8; nt++) cst[mf][nt] = 0.0f;

    auto issue_copy = [&](int c) {
        const float4* src = (const float4*)(wpL + (size_t)c * WCHUNK_U32);
        uint32_t dst = sb + ((c & 1) ? WB1_OFF : WB0_OFF);
        for (int u = tid; u < WCHUNK_U32 / 4; u += 256)
            cpa16(dst + u * 16, src + u);
        cpcommit();
    };

    for (int t = 0; t < T_; ++t) {
        // ---- acc <- xg (fp16, unit-major, bias folded) ----
#pragma unroll
        for (int mf = 0; mf < 4; mf++) {
            const __half* x1 = g_xg + ((size_t)(row0 + mf * 16 + qid) * T_ + t) * G_;
            const __half* x2 = x1 + (size_t)8 * T_ * G_;
#pragma unroll
            for (int nt = 0; nt < 8; nt++) {
                int c = wn * 64 + nt * 8 + 2 * j;
                uint32_t u1 = *(const uint32_t*)(x1 + c);
                uint32_t u2 = *(const uint32_t*)(x2 + c);
                float2 v1 = __half22float2(*(__half2*)&u1);
                float2 v2 = __half22float2(*(__half2*)&u2);
                acc[mf][nt][0] = v1.x; acc[mf][nt][1] = v1.y;
                acc[mf][nt][2] = v2.x; acc[mf][nt][3] = v2.y;
            }
        }
        // ---- layer-0: stream previous step's h to global (fp16, coalesced) ----
        if (layer == 0 && t > 0) {
#pragma unroll
            for (int k = 0; k < 8; k++) {
                int idx = tid + k * 256;
                int r = idx >> 5, c4 = (idx & 31) * 4;
                float4 v = *(const float4*)(hstage + r * HSTRIDE + c4);
                __half2 h0 = __floats2half2_rn(v.x, v.y);
                __half2 h1 = __floats2half2_rn(v.z, v.w);
                uint2 u; u.x = *(uint32_t*)&h0; u.y = *(uint32_t*)&h1;
                *(uint2*)(g_hout0 + ((size_t)(row0 + r) * T_ + (t - 1)) * H_ + c4) = u;
            }
        }
        // ---- h @ Whh^T via fp16 2-term mma, 4 streamed k32 chunks ----
        if (t) {
            for (int c = 0; c < 4; ++c) {
                cpwait0();
                __syncthreads();
                if (c < 3) issue_copy(c + 1);
                const uint32_t* wb = (const uint32_t*)(smem + ((c & 1) ? WB1_OFF : WB0_OFF));
#pragma unroll
                for (int lkt = 0; lkt < 2; ++lkt) {
                    const int kb = c * 16 + lkt * 8 + j;
                    uint32_t ah[4][4], al[4][4];
#pragma unroll
                    for (int mf = 0; mf < 4; ++mf) {
                        const uint32_t* p1 = aphi + (mf * 16 + qid) * 68;
                        const uint32_t* p2 = p1 + 8 * 68;
                        ah[mf][0] = p1[kb];     ah[mf][1] = p2[kb];
                        ah[mf][2] = p1[kb + 4]; ah[mf][3] = p2[kb + 4];
                        const uint32_t* q1 = aplo + (mf * 16 + qid) * 68;
                        const uint32_t* q2 = q1 + 8 * 68;
                        al[mf][0] = q1[kb];     al[mf][1] = q2[kb];
                        al[mf][2] = q1[kb + 4]; al[mf][3] = q2[kb + 4];
                    }
                    const uint32_t* w0 = wb + (lkt * 8 + j) * 520;
                    const uint32_t* w1 = w0 + 4 * 520;
#pragma unroll
                    for (int nt = 0; nt < 8; ++nt) {
                        int n = wn * 64 + nt * 8 + qid;
                        uint32_t bw[2] = { w0[n], w1[n] };
                        mma_f16(acc[0][nt], ah[0], bw);
                        mma_f16(acc[1][nt], ah[1], bw);
                        mma_f16(acc[2][nt], ah[2], bw);
                        mma_f16(acc[3][nt], ah[3], bw);
                        mma_f16(acc[0][nt], al[0], bw);
                        mma_f16(acc[1][nt], al[1], bw);
                        mma_f16(acc[2][nt], al[2], bw);
                        mma_f16(acc[3][nt], al[3], bw);
                    }
                }
            }
        }
        __syncthreads();   // mma done reading AP before rewrite; hstage STG reads done

        // ---- activations: shfl-pair (i,f)<->(g,o), update c, emit h ----
        const bool ev = (lane & 1) == 0;
        const bool keep_h = (layer == 0) || (t == T_ - 1);
#pragma unroll
        for (int mf = 0; mf < 4; ++mf) {
            int r1 = mf * 16 + qid;
#pragma unroll
            for (int nt = 0; nt < 8; ++nt) {
                float x0 = __shfl_xor_sync(0xffffffffu, acc[mf][nt][0], 1);
                float x1 = __shfl_xor_sync(0xffffffffu, acc[mf][nt][1], 1);
                float x2 = __shfl_xor_sync(0xffffffffu, acc[mf][nt][2], 1);
                float x3 = __shfl_xor_sync(0xffffffffu, acc[mf][nt][3], 1);
                float iv = ev ? acc[mf][nt][0] : x2;
                float fv = ev ? acc[mf][nt][1] : x3;
                float gv = ev ? x0 : acc[mf][nt][2];
                float ov = ev ? x1 : acc[mf][nt][3];
                float c = cst[mf][nt];
                c = sgf(fv) * c + sgf(iv) * thf(gv);
                cst[mf][nt] = c;
                float h = sgf(ov) * thf(c);
                int row = ev ? r1 : (r1 + 8);
                int u = wn * 16 + nt * 2 + ((lane >> 1) & 1);
                uint16_t hh = f16b(h);
                uint16_t hl = f16b(h - f16f(hh));
                uint32_t off = (uint32_t)(row * 68 + (u >> 1)) * 4 + (u & 1) * 2;
                *(uint16_t*)(smem + APHI_OFF + off) = hh;
                *(uint16_t*)(smem + APLO_OFF + off) = hl;
                if (keep_h) hstage[row * HSTRIDE + u] = h;
            }
        }
        if (t + 1 < T_) issue_copy(0);   // prefetch chunk0 for next step
        __syncthreads();                 // AP/hstage ready
    } // t

    if (layer == 0) {
        // final h(T-1) -> g_hout0 (fp16)
#pragma unroll
        for (int k = 0; k < 8; k++) {
            int idx = tid + k * 256;
            int r = idx >> 5, c4 = (idx & 31) * 4;
            float4 v = *(const float4*)(hstage + r * HSTRIDE + c4);
            __half2 h0 = __floats2half2_rn(v.x, v.y);
            __half2 h1 = __floats2half2_rn(v.z, v.w);
            uint2 u; u.x = *(uint32_t*)&h0; u.y = *(uint32_t*)&h1;
            *(uint2*)(g_hout0 + ((size_t)(row0 + r) * T_ + (T_ - 1)) * H_ + c4) = u;
        }
        return;
    }

    // =================== dense head (final h in hstage, 64 rows) ===================
    float* lnS = (float*)(smem + WB0_OFF);            // [64][128] -> 32KB (wbuf0 dead)
    float* d1S = (float*)(smem + APHI_OFF);           // [64][128] in AP region (dead)
    float* d2S = lnS;                                 // reuse after d1 built

    if (tid < 64) {
        int r = tid;
        const float* hr = hstage + r * HSTRIDE;
        float s = 0.0f;
        for (int k = 0; k < H_; k++) s += hr[k];
        float mu = s * (1.0f / H_);
        float v = 0.0f;
        for (int k = 0; k < H_; k++) { float d = hr[k] - mu; v += d * d; }
        float rstd = rsqrtf(v * (1.0f / H_) + 1e-5f);
        for (int k = 0; k < H_; k++)
            lnS[r * H_ + k] = (hr[k] - mu) * rstd * __ldg(g_ln + k) + __ldg(be_ln + k);
    }
    __syncthreads();

    // d1 = relu(ln @ W_d1^T + b_d1): weights direct from global (L1/L2-cached)
    {
        int r = tid >> 2, c0 = (tid & 3) * 32;
        for (int c = c0; c < c0 + 32; c++) {
            float a = __ldg(b_d1 + c);
            const float4* lp = (const float4*)(lnS + r * H_);
            const float4* wp = (const float4*)(W_d1 + (size_t)c * H_);
#pragma unroll 8
            for (int k4 = 0; k4 < H_ / 4; k4++) {
                float4 l = lp[k4], w = __ldg(wp + k4);
                a = fmaf(l.x, w.x, fmaf(l.y, w.y, fmaf(l.z, w.z, fmaf(l.w, w.w, a))));
            }
            d1S[r * D1_ + c] = fmaxf(a, 0.0f);
        }
    }
    __syncthreads();

    // d2 = relu(d1 @ W_d2^T + b_d2)
    {
        int r = tid >> 2, c0 = (tid & 3) * 16;
        for (int c = c0; c < c0 + 16; c++) {
            float a = __ldg(b_d2 + c);
            const float4* dp = (const float4*)(d1S + r * D1_);
            const float4* wp = (const float4*)(W_d2 + (size_t)c * D1_);
#pragma unroll 8
            for (int k4 = 0; k4 < D1_ / 4; k4++) {
                float4 l = dp[k4], w = __ldg(wp + k4);
                a = fmaf(l.x, w.x, fmaf(l.y, w.y, fmaf(l.z, w.z, fmaf(l.w, w.w, a))));
            }
            d2S[r * D2_ + c] = fmaxf(a, 0.0f);
        }
    }
    __syncthreads();

    // out = d2 @ W_d3^T + b_d3
    for (int idx = tid; idx < 64 * OUT_; idx += 256) {
        int r = idx / OUT_, c = idx % OUT_;
        float a = __ldg(b_d3 + c);
        const float* dp = d2S + r * D2_;
        const float* wp = W_d3 + (size_t)c * D2_;
#pragma unroll 8
        for (int k = 0; k < D2_; k++) a = fmaf(dp[k], __ldg(wp + k), a);
        out[(size_t)(row0 + r) * OUT_ + c] = a;
    }
}

// ======================= launch =======================
extern "C" void kernel_launch(void* const* d_in, const int* in_sizes, int n_in,
                              void* d_out, int out_size) {
    (void)in_sizes; (void)n_in; (void)out_size;
    const float* x     = (const float*)d_in[0];
    const float* W_in  = (const float*)d_in[1];
    const float* b_in  = (const float*)d_in[2];
    const float* g_in  = (const float*)d_in[3];
    const float* be_in = (const float*)d_in[4];
    const float* Wih0  = (const float*)d_in[5];
    const float* Whh0  = (const float*)d_in[6];
    const float* bih0  = (const float*)d_in[7];
    const float* bhh0  = (const float*)d_in[8];
    const float* Wih1  = (const float*)d_in[9];
    const float* Whh1  = (const float*)d_in[10];
    const float* bih1  = (const float*)d_in[11];
    const float* bhh1  = (const float*)d_in[12];
    const float* g_ln  = (const float*)d_in[13];
    const float* be_ln = (const float*)d_in[14];
    const float* W_d1  = (const float*)d_in[15];
    const float* b_d1  = (const float*)d_in[16];
    const float* W_d2  = (const float*)d_in[17];
    const float* b_d2  = (const float*)d_in[18];
    const float* W_d3  = (const float*)d_in[19];
    const float* b_d3  = (const float*)d_in[20];
    float* out = (float*)d_out;

    cudaFuncSetAttribute(gemm_xg_kernel, cudaFuncAttributeMaxDynamicSharedMemorySize, GX2_SMEM);
    cudaFuncSetAttribute(lstm_seq_kernel, cudaFuncAttributeMaxDynamicSharedMemorySize, SQ_SMEM);

    prep_kernel<<<260, 256>>>(Whh0, bih0, bhh0, Whh1, bih1, bhh1);
    proj_ln_kernel<<<(B_ * T_) / 8, 256>>>(x, W_in, b_in, g_in, be_in);

    gemm_xg_kernel<<<148, 256, GX2_SMEM>>>(Wih0, Wih1, 0);
    lstm_seq_kernel<<<B_ / 64, 256, SQ_SMEM>>>(0, g_ln, be_ln, W_d1, b_d1,
                                               W_d2, b_d2, W_d3, b_d3, out);
    gemm_xg_kernel<<<148, 256, GX2_SMEM>>>(Wih0, Wih1, 1);
    lstm_seq_kernel<<<B_ / 64, 256, SQ_SMEM>>>(1, g_ln, be_ln, W_d1, b_d1,
                                               W_d2, b_d2, W_d3, b_d3, out);
}

// round 17
// speedup vs baseline: 1.3593x; 1.1401x over previous
#include <cuda_runtime.h>
#include <cuda_fp16.h>
#include <cstdint>
#include <cstddef>

#define B_    8192
#define T_    90
#define F_    7
#define H_    128
#define G_    512      // 4*H
#define D1_   128
#define D2_   64
#define OUT_  30

// -------- device scratch (no cudaMalloc allowed) --------
__device__ __align__(128) __half g_hin  [(size_t)B_ * T_ * H_];  // LN(x@W_in^T+b), fp16
__device__ __align__(128) __half g_hout0[(size_t)B_ * T_ * H_];  // layer-0 h outs, fp16
__device__ __align__(128) __half g_xg   [(size_t)B_ * T_ * G_];  // input projections (+bias), fp16, unit-major
// Whh packed fp16 k-pair fragments (single term): [L][chunk 4][kk 16][520] u32
__device__ __align__(128) uint32_t g_WP[2 * 4 * 16 * 520];
__device__ float g_biasC[2 * G_];   // bih + bhh, unit-major order

// ======================= common helpers =======================
__device__ __forceinline__ float sgf(float x) {
    return __fdividef(1.0f, 1.0f + __expf(-x));
}
__device__ __forceinline__ float thf(float x) {
    return 2.0f * sgf(2.0f * x) - 1.0f;
}
__device__ __forceinline__ uint16_t f16b(float x) {
    __half h = __float2half_rn(x);
    return *(uint16_t*)&h;
}
__device__ __forceinline__ void cpa16(uint32_t s, const void* g) {
    asm volatile("cp.async.cg.shared.global [%0], [%1], 16;" :: "r"(s), "l"(g));
}
__device__ __forceinline__ void cpcommit() { asm volatile("cp.async.commit_group;"); }
__device__ __forceinline__ void cpwait0()  { asm volatile("cp.async.wait_group 0;"); }
__device__ __forceinline__ uint32_t smem_u32(const void* p) {
    uint32_t a;
    asm("{ .reg .u64 t; cvta.to.shared.u64 t, %1; cvt.u32.u64 %0, t; }" : "=r"(a) : "l"(p));
    return a;
}
// portable tensor-core mma (sm_80+ PTX, runs as HMMA on sm_103)
__device__ __forceinline__ void mma_f16(float* d, const uint32_t* a, const uint32_t* b) {
    asm("mma.sync.aligned.m16n8k16.row.col.f32.f16.f16.f32 "
        "{%0,%1,%2,%3}, {%4,%5,%6,%7}, {%8,%9}, {%0,%1,%2,%3};"
        : "+f"(d[0]), "+f"(d[1]), "+f"(d[2]), "+f"(d[3])
        : "r"(a[0]), "r"(a[1]), "r"(a[2]), "r"(a[3]), "r"(b[0]), "r"(b[1]));
}

// ======================= K0: weight repack =======================
// n_phys = unit*4 + gate (gate: 0=i,1=f,2=g,3=o); source row = gate*128 + unit.
// g_WP[L][c4][kk16][520]: u32 = pack(fp16 W[k0], fp16 W[k0+1]), k0 = c*32 + kk*2.
__global__ void prep_kernel(const float* __restrict__ Whh0, const float* __restrict__ bih0,
                            const float* __restrict__ bhh0, const float* __restrict__ Whh1,
                            const float* __restrict__ bih1, const float* __restrict__ bhh1) {
    int idx = blockIdx.x * blockDim.x + threadIdx.x;
    const int per_l = 4 * 16 * 520;   // 33280 per layer
    if (idx < 2 * per_l) {
        int L = idx / per_l;
        int r = idx % per_l;
        int c = r / (16 * 520);
        int kk = (r / 520) % 16;
        int n = r % 520;
        uint32_t p = 0;
        if (n < 512) {
            const float* Whh = L ? Whh1 : Whh0;
            int u = n >> 2, g = n & 3;
            const float* src = Whh + (size_t)(g * 128 + u) * H_ + (c * 32 + kk * 2);
            p = ((uint32_t)f16b(src[1]) << 16) | f16b(src[0]);
        }
        g_WP[((L * 4 + c) * 16 + kk) * 520 + n] = p;
    }
    if (idx < 2 * G_) {
        int L = idx >> 9, n = idx & 511;
        int u = n >> 2, g = n & 3;
        const float* bih = L ? bih1 : bih0;
        const float* bhh = L ? bhh1 : bhh0;
        g_biasC[idx] = bih[g * 128 + u] + bhh[g * 128 + u];
    }
}

// ============ K1: input projection + layernorm (warp per row, fp16 out) ============
__global__ void __launch_bounds__(256) proj_ln_kernel(
    const float* __restrict__ x, const float* __restrict__ W_in,
    const float* __restrict__ b_in, const float* __restrict__ g_in,
    const float* __restrict__ be_in) {
    __shared__ float Ws[H_ * F_];
    __shared__ float bs[H_], gs[H_], es[H_];
    int tid = threadIdx.x;
    for (int i = tid; i < H_ * F_; i += 256) Ws[i] = W_in[i];
    if (tid < H_) { bs[tid] = b_in[tid]; gs[tid] = g_in[tid]; es[tid] = be_in[tid]; }
    __syncthreads();

    int warp = tid >> 5, lane = tid & 31;
    int row = blockIdx.x * 8 + warp;

    float xv = (lane < F_) ? x[(size_t)row * F_ + lane] : 0.0f;
    float y[4];
#pragma unroll
    for (int j = 0; j < 4; j++) {
        int h = lane * 4 + j;             // contiguous 4 per lane -> vector store
        float a = bs[h];
#pragma unroll
        for (int f = 0; f < F_; f++) {
            float xf = __shfl_sync(0xffffffffu, xv, f);
            a = fmaf(xf, Ws[h * F_ + f], a);
        }
        y[j] = a;
    }
    float s = y[0] + y[1] + y[2] + y[3];
#pragma unroll
    for (int o = 16; o; o >>= 1) s += __shfl_xor_sync(0xffffffffu, s, o);
    float mu = s * (1.0f / H_);
    float v = 0.0f;
#pragma unroll
    for (int j = 0; j < 4; j++) { float d = y[j] - mu; v += d * d; }
#pragma unroll
    for (int o = 16; o; o >>= 1) v += __shfl_xor_sync(0xffffffffu, v, o);
    float rstd = rsqrtf(v * (1.0f / H_) + 1e-5f);

    float o[4];
#pragma unroll
    for (int j = 0; j < 4; j++) {
        int h = lane * 4 + j;
        o[j] = (y[j] - mu) * rstd * gs[h] + es[h];
    }
    __half2 p0 = __floats2half2_rn(o[0], o[1]);
    __half2 p1 = __floats2half2_rn(o[2], o[3]);
    uint2 u;
    u.x = *(uint32_t*)&p0;
    u.y = *(uint32_t*)&p1;
    *(uint2*)(g_hin + (size_t)row * H_ + lane * 4) = u;
}

// ============ K2: xg = in @ Wih^T + bias   (mma.sync fp16, unit-major cols) ============
// CTA 256 thr, tile 128M x 256N, K=128. warps 2m x 4n, warp tile 64x64.
// smem: As u32[128][68] 34816 | Bs u32[256][68] 69632 | bias 1KB = 105472 B
#define GX2_OFF_B   34816
#define GX2_OFF_BI  104448
#define GX2_SMEM    105472
#define N_MTILES    ((B_ * T_) / 128)   // 5760

__global__ void __launch_bounds__(256, 1) gemm_xg_kernel(
    const float* __restrict__ Wih0, const float* __restrict__ Wih1, int layer) {
    extern __shared__ char smem[];
    uint32_t* As = (uint32_t*)smem;                   // [128][68] fp16 pairs
    uint32_t* Bs = (uint32_t*)(smem + GX2_OFF_B);     // [256][68] fp16 pairs
    float* biasS = (float*)(smem + GX2_OFF_BI);
    const uint32_t asAddr = smem_u32(As);

    const int tid  = threadIdx.x;
    const int lane = tid & 31, wid = tid >> 5;
    const int wm = wid & 1, wn = wid >> 1;
    const int lrow = lane >> 2, lcol = lane & 3;
    const int nh = blockIdx.x & 1, slot = blockIdx.x >> 1;

    const __half* in = layer ? g_hout0 : g_hin;
    const float* W   = layer ? Wih1 : Wih0;   // indexed via n_phys mapping

    // ---- one-time: weights -> smem fp16, bias ----
    for (int idx = tid; idx < 256 * H_; idx += 256) {
        int n = idx >> 7, k = idx & 127;
        int np = nh * 256 + n;               // physical (unit-major) column
        float w = W[(size_t)((np & 3) * 128 + (np >> 2)) * H_ + k];
        *(uint16_t*)(smem + GX2_OFF_B + (n * 68 + (k >> 1)) * 4 + (k & 1) * 2) = f16b(w);
    }
    for (int i = tid; i < 256; i += 256) biasS[i] = g_biasC[layer * G_ + nh * 256 + i];
    __syncthreads();

    float bC[8][2];
#pragma unroll
    for (int nf = 0; nf < 8; nf++) {
        int c = wn * 64 + nf * 8 + 2 * lcol;
        bC[nf][0] = biasS[c];
        bC[nf][1] = biasS[c + 1];
    }

    auto copyA = [&](int m0) {
#pragma unroll 4
        for (int u = tid; u < 2048; u += 256) {
            int r = u >> 4, q = u & 15;     // 16B = 8 halves per chunk
            cpa16(asAddr + (uint32_t)(r * 68 + q * 4) * 4,
                  in + (size_t)(m0 + r) * H_ + q * 8);
        }
        cpcommit();
    };

    int mt = slot;
    if (mt < N_MTILES) copyA(mt * 128);
    for (; mt < N_MTILES; mt += 74) {
        const int m0 = mt * 128;
        cpwait0();
        __syncthreads();

        float acc[4][8][4];
#pragma unroll
        for (int mf = 0; mf < 4; mf++)
#pragma unroll
            for (int nf = 0; nf < 8; nf++)
#pragma unroll
                for (int q = 0; q < 4; q++) acc[mf][nf][q] = 0.0f;

#pragma unroll
        for (int kbb = 0; kbb < 8; kbb++) {    // k16 blocks
            uint32_t a[4][4], b[8][2];
#pragma unroll
            for (int mf = 0; mf < 4; mf++) {
                const uint32_t* Ar = As + (wm * 64 + mf * 16 + lrow) * 68 + kbb * 8;
                a[mf][0] = Ar[lcol];
                a[mf][1] = Ar[8 * 68 + lcol];
                a[mf][2] = Ar[lcol + 4];
                a[mf][3] = Ar[8 * 68 + lcol + 4];
            }
#pragma unroll
            for (int nf = 0; nf < 8; nf++) {
                const uint32_t* Br = Bs + (wn * 64 + nf * 8 + lrow) * 68 + kbb * 8;
                b[nf][0] = Br[lcol];
                b[nf][1] = Br[lcol + 4];
            }
#pragma unroll
            for (int mf = 0; mf < 4; mf++)
#pragma unroll
                for (int nf = 0; nf < 8; nf++)
                    mma_f16(acc[mf][nf], a[mf], b[nf]);
        }
        __syncthreads();
        if (mt + 74 < N_MTILES) copyA((mt + 74) * 128);

        // ---- epilogue: bias add + fp16 store ----
#pragma unroll
        for (int mf = 0; mf < 4; mf++) {
            int r0 = m0 + wm * 64 + mf * 16 + lrow;
            __half* o0 = g_xg + (size_t)r0 * G_ + nh * 256 + wn * 64;
            __half* o1 = o0 + (size_t)8 * G_;
#pragma unroll
            for (int nf = 0; nf < 8; nf++) {
                int c = nf * 8 + 2 * lcol;
                __half2 v0 = __floats2half2_rn(acc[mf][nf][0] + bC[nf][0],
                                               acc[mf][nf][1] + bC[nf][1]);
                __half2 v1 = __floats2half2_rn(acc[mf][nf][2] + bC[nf][0],
                                               acc[mf][nf][3] + bC[nf][1]);
                *(uint32_t*)(o0 + c) = *(uint32_t*)&v0;
                *(uint32_t*)(o1 + c) = *(uint32_t*)&v1;
            }
        }
    }
}

// ============ K3: sequential recurrence (fp16 SINGLE-term mma, streamed weights) ============
// 128 CTAs x 256 threads (8 warps, 1m x 8n), 64 batch rows per CTA.
// smem map (117760 B/CTA):
//   [0,17408)        AP  u32[64][68]   (h packed fp16 pairs, k = unit)
//   [17408,51200)    hstage f32[64][132]
//   [51200,84480)    wbuf0: [kk16][520] u32 (33280 B)
//   [84480,117760)   wbuf1
#define APHI_OFF   0
#define HST_OFF    17408
#define HSTRIDE    132
#define WB0_OFF    51200
#define WB1_OFF    84480
#define WCHUNK_U32 (16 * 520)   // 8320
#define SQ_SMEM    117760

__global__ void __launch_bounds__(256, 1) lstm_seq_kernel(
    int layer,
    const float* __restrict__ g_ln, const float* __restrict__ be_ln,
    const float* __restrict__ W_d1, const float* __restrict__ b_d1,
    const float* __restrict__ W_d2, const float* __restrict__ b_d2,
    const float* __restrict__ W_d3, const float* __restrict__ b_d3,
    float* __restrict__ out) {
    extern __shared__ char smem[];
    float* hstage = (float*)(smem + HST_OFF);
    const uint32_t* aphi = (const uint32_t*)(smem + APHI_OFF);

    const int tid = threadIdx.x;
    const int lane = tid & 31, wn = tid >> 5;
    const int qid = lane >> 2, j = lane & 3;
    const int row0 = blockIdx.x * 64;
    const uint32_t sb = smem_u32(smem);
    const uint32_t* wpL = g_WP + (size_t)layer * 4 * WCHUNK_U32;

    float acc[4][8][4];
    float cst[4][8];
#pragma unroll
    for (int mf = 0; mf < 4; mf++)
#pragma unroll
        for (int nt = 0; nt < 8; nt++) cst[mf][nt] = 0.0f;

    auto issue_copy = [&](int c) {
        const float4* src = (const float4*)(wpL + (size_t)c * WCHUNK_U32);
        uint32_t dst = sb + ((c & 1) ? WB1_OFF : WB0_OFF);
        for (int u = tid; u < WCHUNK_U32 / 4; u += 256)
            cpa16(dst + u * 16, src + u);
        cpcommit();
    };

    for (int t = 0; t < T_; ++t) {
        // ---- acc <- xg (fp16, unit-major, bias folded) ----
#pragma unroll
        for (int mf = 0; mf < 4; mf++) {
            const __half* x1 = g_xg + ((size_t)(row0 + mf * 16 + qid) * T_ + t) * G_;
            const __half* x2 = x1 + (size_t)8 * T_ * G_;
#pragma unroll
            for (int nt = 0; nt < 8; nt++) {
                int c = wn * 64 + nt * 8 + 2 * j;
                uint32_t u1 = *(const uint32_t*)(x1 + c);
                uint32_t u2 = *(const uint32_t*)(x2 + c);
                float2 v1 = __half22float2(*(__half2*)&u1);
                float2 v2 = __half22float2(*(__half2*)&u2);
                acc[mf][nt][0] = v1.x; acc[mf][nt][1] = v1.y;
                acc[mf][nt][2] = v2.x; acc[mf][nt][3] = v2.y;
            }
        }
        // ---- layer-0: stream previous step's h to global (fp16, coalesced) ----
        if (layer == 0 && t > 0) {
#pragma unroll
            for (int k = 0; k < 8; k++) {
                int idx = tid + k * 256;
                int r = idx >> 5, c4 = (idx & 31) * 4;
                float4 v = *(const float4*)(hstage + r * HSTRIDE + c4);
                __half2 h0 = __floats2half2_rn(v.x, v.y);
                __half2 h1 = __floats2half2_rn(v.z, v.w);
                uint2 u; u.x = *(uint32_t*)&h0; u.y = *(uint32_t*)&h1;
                *(uint2*)(g_hout0 + ((size_t)(row0 + r) * T_ + (t - 1)) * H_ + c4) = u;
            }
        }
        // ---- h @ Whh^T via fp16 single-term mma, 4 streamed k32 chunks ----
        if (t) {
            for (int c = 0; c < 4; ++c) {
                cpwait0();
                __syncthreads();
                if (c < 3) issue_copy(c + 1);
                const uint32_t* wb = (const uint32_t*)(smem + ((c & 1) ? WB1_OFF : WB0_OFF));
#pragma unroll
                for (int lkt = 0; lkt < 2; ++lkt) {
                    const int kb = c * 16 + lkt * 8 + j;
                    uint32_t ah[4][4];
#pragma unroll
                    for (int mf = 0; mf < 4; ++mf) {
                        const uint32_t* p1 = aphi + (mf * 16 + qid) * 68;
                        const uint32_t* p2 = p1 + 8 * 68;
                        ah[mf][0] = p1[kb];     ah[mf][1] = p2[kb];
                        ah[mf][2] = p1[kb + 4]; ah[mf][3] = p2[kb + 4];
                    }
                    const uint32_t* w0 = wb + (lkt * 8 + j) * 520;
                    const uint32_t* w1 = w0 + 4 * 520;
#pragma unroll
                    for (int nt = 0; nt < 8; ++nt) {
                        int n = wn * 64 + nt * 8 + qid;
                        uint32_t bw[2] = { w0[n], w1[n] };
                        mma_f16(acc[0][nt], ah[0], bw);
                        mma_f16(acc[1][nt], ah[1], bw);
                        mma_f16(acc[2][nt], ah[2], bw);
                        mma_f16(acc[3][nt], ah[3], bw);
                    }
                }
            }
        }
        __syncthreads();   // mma done reading AP before rewrite; hstage STG reads done

        // ---- activations: shfl-pair (i,f)<->(g,o), update c, emit h ----
        const bool ev = (lane & 1) == 0;
        const bool keep_h = (layer == 0) || (t == T_ - 1);
#pragma unroll
        for (int mf = 0; mf < 4; ++mf) {
            int r1 = mf * 16 + qid;
#pragma unroll
            for (int nt = 0; nt < 8; ++nt) {
                float x0 = __shfl_xor_sync(0xffffffffu, acc[mf][nt][0], 1);
                float x1 = __shfl_xor_sync(0xffffffffu, acc[mf][nt][1], 1);
                float x2 = __shfl_xor_sync(0xffffffffu, acc[mf][nt][2], 1);
                float x3 = __shfl_xor_sync(0xffffffffu, acc[mf][nt][3], 1);
                float iv = ev ? acc[mf][nt][0] : x2;
                float fv = ev ? acc[mf][nt][1] : x3;
                float gv = ev ? x0 : acc[mf][nt][2];
                float ov = ev ? x1 : acc[mf][nt][3];
                float c = cst[mf][nt];
                c = sgf(fv) * c + sgf(iv) * thf(gv);
                cst[mf][nt] = c;
                float h = sgf(ov) * thf(c);
                int row = ev ? r1 : (r1 + 8);
                int u = wn * 16 + nt * 2 + ((lane >> 1) & 1);
                uint32_t off = (uint32_t)(row * 68 + (u >> 1)) * 4 + (u & 1) * 2;
                *(uint16_t*)(smem + APHI_OFF + off) = f16b(h);
                if (keep_h) hstage[row * HSTRIDE + u] = h;
            }
        }
        if (t + 1 < T_) issue_copy(0);   // prefetch chunk0 for next step
        __syncthreads();                 // AP/hstage ready
    } // t

    if (layer == 0) {
        // final h(T-1) -> g_hout0 (fp16)
#pragma unroll
        for (int k = 0; k < 8; k++) {
            int idx = tid + k * 256;
            int r = idx >> 5, c4 = (idx & 31) * 4;
            float4 v = *(const float4*)(hstage + r * HSTRIDE + c4);
            __half2 h0 = __floats2half2_rn(v.x, v.y);
            __half2 h1 = __floats2half2_rn(v.z, v.w);
            uint2 u; u.x = *(uint32_t*)&h0; u.y = *(uint32_t*)&h1;
            *(uint2*)(g_hout0 + ((size_t)(row0 + r) * T_ + (T_ - 1)) * H_ + c4) = u;
        }
        return;
    }

    // =================== dense head (final h in hstage, 64 rows) ===================
    float* lnS = (float*)(smem + WB0_OFF);            // [64][128] = 32KB (wbuf0 dead)
    float* d1S = (float*)(smem + WB1_OFF);            // [64][128] = 32KB (wbuf1 dead)
    float* d2S = lnS;                                 // reuse after d1 built

    if (tid < 64) {
        int r = tid;
        const float* hr = hstage + r * HSTRIDE;
        float s = 0.0f;
        for (int k = 0; k < H_; k++) s += hr[k];
        float mu = s * (1.0f / H_);
        float v = 0.0f;
        for (int k = 0; k < H_; k++) { float d = hr[k] - mu; v += d * d; }
        float rstd = rsqrtf(v * (1.0f / H_) + 1e-5f);
        for (int k = 0; k < H_; k++)
            lnS[r * H_ + k] = (hr[k] - mu) * rstd * __ldg(g_ln + k) + __ldg(be_ln + k);
    }
    __syncthreads();

    // d1 = relu(ln @ W_d1^T + b_d1): weights direct from global (L1/L2-cached)
    {
        int r = tid >> 2, c0 = (tid & 3) * 32;
        for (int c = c0; c < c0 + 32; c++) {
            float a = __ldg(b_d1 + c);
            const float4* lp = (const float4*)(lnS + r * H_);
            const float4* wp = (const float4*)(W_d1 + (size_t)c * H_);
#pragma unroll 8
            for (int k4 = 0; k4 < H_ / 4; k4++) {
                float4 l = lp[k4], w = __ldg(wp + k4);
                a = fmaf(l.x, w.x, fmaf(l.y, w.y, fmaf(l.z, w.z, fmaf(l.w, w.w, a))));
            }
            d1S[r * D1_ + c] = fmaxf(a, 0.0f);
        }
    }
    __syncthreads();

    // d2 = relu(d1 @ W_d2^T + b_d2)
    {
        int r = tid >> 2, c0 = (tid & 3) * 16;
        for (int c = c0; c < c0 + 16; c++) {
            float a = __ldg(b_d2 + c);
            const float4* dp = (const float4*)(d1S + r * D1_);
            const float4* wp = (const float4*)(W_d2 + (size_t)c * D1_);
#pragma unroll 8
            for (int k4 = 0; k4 < D1_ / 4; k4++) {
                float4 l = dp[k4], w = __ldg(wp + k4);
                a = fmaf(l.x, w.x, fmaf(l.y, w.y, fmaf(l.z, w.z, fmaf(l.w, w.w, a))));
            }
            d2S[r * D2_ + c] = fmaxf(a, 0.0f);
        }
    }
    __syncthreads();

    // out = d2 @ W_d3^T + b_d3
    for (int idx = tid; idx < 64 * OUT_; idx += 256) {
        int r = idx / OUT_, c = idx % OUT_;
        float a = __ldg(b_d3 + c);
        const float* dp = d2S + r * D2_;
        const float* wp = W_d3 + (size_t)c * D2_;
#pragma unroll 8
        for (int k = 0; k < D2_; k++) a = fmaf(dp[k], __ldg(wp + k), a);
        out[(size_t)(row0 + r) * OUT_ + c] = a;
    }
}

// ======================= launch =======================
extern "C" void kernel_launch(void* const* d_in, const int* in_sizes, int n_in,
                              void* d_out, int out_size) {
    (void)in_sizes; (void)n_in; (void)out_size;
    const float* x     = (const float*)d_in[0];
    const float* W_in  = (const float*)d_in[1];
    const float* b_in  = (const float*)d_in[2];
    const float* g_in  = (const float*)d_in[3];
    const float* be_in = (const float*)d_in[4];
    const float* Wih0  = (const float*)d_in[5];
    const float* Whh0  = (const float*)d_in[6];
    const float* bih0  = (const float*)d_in[7];
    const float* bhh0  = (const float*)d_in[8];
    const float* Wih1  = (const float*)d_in[9];
    const float* Whh1  = (const float*)d_in[10];
    const float* bih1  = (const float*)d_in[11];
    const float* bhh1  = (const float*)d_in[12];
    const float* g_ln  = (const float*)d_in[13];
    const float* be_ln = (const float*)d_in[14];
    const float* W_d1  = (const float*)d_in[15];
    const float* b_d1  = (const float*)d_in[16];
    const float* W_d2  = (const float*)d_in[17];
    const float* b_d2  = (const float*)d_in[18];
    const float* W_d3  = (const float*)d_in[19];
    const float* b_d3  = (const float*)d_in[20];
    float* out = (float*)d_out;

    cudaFuncSetAttribute(gemm_xg_kernel, cudaFuncAttributeMaxDynamicSharedMemorySize, GX2_SMEM);
    cudaFuncSetAttribute(lstm_seq_kernel, cudaFuncAttributeMaxDynamicSharedMemorySize, SQ_SMEM);

    prep_kernel<<<260, 256>>>(Whh0, bih0, bhh0, Whh1, bih1, bhh1);
    proj_ln_kernel<<<(B_ * T_) / 8, 256>>>(x, W_in, b_in, g_in, be_in);

    gemm_xg_kernel<<<148, 256, GX2_SMEM>>>(Wih0, Wih1, 0);
    lstm_seq_kernel<<<B_ / 64, 256, SQ_SMEM>>>(0, g_ln, be_ln, W_d1, b_d1,
                                               W_d2, b_d2, W_d3, b_d3, out);
    gemm_xg_kernel<<<148, 256, GX2_SMEM>>>(Wih0, Wih1, 1);
    lstm_seq_kernel<<<B_ / 64, 256, SQ_SMEM>>>(1, g_ln, be_ln, W_d1, b_d1,
                                               W_d2, b_d2, W_d3, b_d3, out);
}